// round 16
// baseline (speedup 1.0000x reference)
#include <cuda_runtime.h>
#include <cuda_fp16.h>

#define DDIM 64
#define KCODES 512
#define NTHREADS 512
#define WARPS 16
#define CHUNK 64
#define CAPL 3
#define NMCAP 12
#define AS 36
#define BS 36
#define MAXG 128

typedef unsigned int u32;
typedef unsigned short u16;

__device__ float  g_embT[KCODES * DDIM];
__device__ double g_partial[MAXG];
__device__ unsigned g_count;

struct SMT {
    u32   B[KCODES * BS];                  // fp16 pairs, row k: word p = d(2p,2p+1)
    u32   Aslice[WARPS * 16 * AS];         // per-warp 16-row ldmatrix staging
    u32   clist[WARPS * CHUNK * 4 * CAPL]; // (f16score_rd<<16)|code
    float ens[KCODES];
    float rowminS[WARPS * CHUNK];
    unsigned char cntS[WARPS * CHUNK * 4];
    u16   codesS[WARPS * CHUNK];
    double lossw[WARPS];
    double red[MAXG];
    float redf[WARPS];
    float epsv;
    int   flag;
};

__device__ __forceinline__ u32 smem_u32(const void* p) {
    u32 a;
    asm("{ .reg .u64 t; cvta.to.shared.u64 t, %1; cvt.u32.u64 %0, t; }" : "=r"(a) : "l"(p));
    return a;
}
__device__ __forceinline__ void mma16816(float* c, const u32* a, const u32* b) {
    asm volatile("mma.sync.aligned.m16n8k16.row.col.f32.f16.f16.f32 "
        "{%0,%1,%2,%3},{%4,%5,%6,%7},{%8,%9},{%0,%1,%2,%3};\n"
        : "+f"(c[0]), "+f"(c[1]), "+f"(c[2]), "+f"(c[3])
        : "r"(a[0]), "r"(a[1]), "r"(a[2]), "r"(a[3]), "r"(b[0]), "r"(b[1]));
}
__device__ __forceinline__ void ldsm4(u32& a0, u32& a1, u32& a2, u32& a3, u32 addr) {
    asm volatile("ldmatrix.sync.aligned.m8n8.x4.shared.b16 {%0,%1,%2,%3}, [%4];"
                 : "=r"(a0), "=r"(a1), "=r"(a2), "=r"(a3) : "r"(addr));
}

// capture: keep CAPL smallest; evict-largest; overflow if victim could matter
__device__ __forceinline__ void capture(u32* cl, float s, int code, float gate, int& cnt) {
    if (s <= gate) {
        u32 ent = ((u32)__half_as_ushort(__float2half_rd(s)) << 16) | (u32)code;
        if (cnt < CAPL) { cl[cnt] = ent; cnt++; }
        else if (cnt == CAPL) {
            int jm = 0;
            float vm = __half2float(__ushort_as_half((u16)(cl[0] >> 16)));
            #pragma unroll
            for (int j = 1; j < CAPL; j++) {
                float vj = __half2float(__ushort_as_half((u16)(cl[j] >> 16)));
                if (vj > vm) { vm = vj; jm = j; }
            }
            if (vm <= gate) cnt = 100;          // overflow -> exact fallback
            else if (s < vm) cl[jm] = ent;
        }
    }
}

__global__ void vq_prep(const float* __restrict__ emb)
{
    int i = blockIdx.x * blockDim.x + threadIdx.x;
    int d = i >> 9, k = i & 511;
    g_embT[k * DDIM + d] = emb[i];
}

__global__ __launch_bounds__(NTHREADS, 1)
void vq_main(const float* __restrict__ x, const float* __restrict__ emb,
             float* __restrict__ out, long nrows, long nelem, int writeLoss)
{
    extern __shared__ char smraw[];
    SMT* smp = (SMT*)smraw;
    const int t = threadIdx.x, lane = t & 31, warp = t >> 5;
    const int gid = lane >> 2, tig = lane & 3;

    // ---- prologue (only block-synced section) ----
    {   // B[k][d] fp16 smem
        int p = t & 31, kg = t >> 5;
        for (int j = 0; j < 32; j++) {
            int k = kg * 32 + j;
            __half2 h = __floats2half2_rn(emb[(2 * p) * KCODES + k],
                                          emb[(2 * p + 1) * KCODES + k]);
            smp->B[k * BS + p] = *(u32*)&h;
        }
    }
    {   // exact ||e_k||^2 (reference chain)
        float s = 0.f;
        #pragma unroll
        for (int d = 0; d < DDIM; d++) {
            float e = emb[d * KCODES + t];
            s = __fadd_rn(s, __fmul_rn(e, e));
        }
        smp->ens[t] = s;
    }
    __syncthreads();
    {   // eps = 0.0625*emax + 1e-3
        float mx = smp->ens[t];
        #pragma unroll
        for (int o = 16; o > 0; o >>= 1) mx = fmaxf(mx, __shfl_xor_sync(~0u, mx, o));
        if (lane == 0) smp->redf[warp] = mx;
        __syncthreads();
        if (t == 0) {
            float m2 = smp->redf[0];
            for (int i = 1; i < WARPS; i++) m2 = fmaxf(m2, smp->redf[i]);
            smp->epsv = 0.0625f * sqrtf(m2) + 1e-3f;
        }
    }
    __syncthreads();

    const float eps = smp->epsv;
    const long chunkrow = ((long)blockIdx.x * WARPS + warp) * CHUNK;
    double lossacc = 0.0;

    if (chunkrow < nrows) {
        const int matid = lane >> 3;
        const int rowoff = ((matid & 1) << 3) + (lane & 7);
        const int kcolw = (matid >> 1) << 2;
        const u32 Asl = smem_u32(&smp->Aslice[warp * 16 * AS]);
        const u32 Bu  = smem_u32(smp->B);

        // ---- stage 64 rows -> A fragments in registers ----
        u32 afr[4][4][4];
        #pragma unroll
        for (int mb = 0; mb < 4; mb++) {
            const float4* xp = (const float4*)(x + (chunkrow + mb * 16) * DDIM);
            #pragma unroll
            for (int i = 0; i < 8; i++) {
                float4 v = xp[lane + 32 * i];
                int q = lane + 32 * i, row = q >> 4, quad = q & 15;
                __half2 h0 = __floats2half2_rn(v.x, v.y);
                __half2 h1 = __floats2half2_rn(v.z, v.w);
                uint2 u; u.x = *(u32*)&h0; u.y = *(u32*)&h1;
                *(uint2*)&smp->Aslice[warp * 16 * AS + row * AS + quad * 2] = u;
            }
            __syncwarp();
            u32 ab = Asl + (u32)(((rowoff * AS + kcolw)) << 2);
            #pragma unroll
            for (int kk = 0; kk < 4; kk++)
                ldsm4(afr[mb][kk][0], afr[mb][kk][1], afr[mb][kk][2], afr[mb][kk][3],
                      ab + (kk << 5));
            __syncwarp();
        }

        // ---- single MMA sweep over 512 codes, warp-private capture ----
        float runmin[8]; int cnt[8];
        #pragma unroll
        for (int i = 0; i < 8; i++) { runmin[i] = 3.4e38f; cnt[i] = 0; }
        const int grp = lane >> 3;
        const int khb = ((grp >> 1) << 4) + ((grp & 1) << 3);

        #pragma unroll 1
        for (int ntl = 0; ntl < 64; ntl++) {
            const int c0 = ntl * 8;
            u32 ba = Bu + (u32)(((c0 + (lane & 7)) * BS) << 2) + (u32)(khb << 1);
            u32 b[4][2];
            ldsm4(b[0][0], b[0][1], b[1][0], b[1][1], ba);
            ldsm4(b[2][0], b[2][1], b[3][0], b[3][1], ba + 64);
            float2 enp = *(const float2*)&smp->ens[c0 + 2 * tig];

            #pragma unroll
            for (int mb = 0; mb < 4; mb++) {
                float acc[4] = {0.f, 0.f, 0.f, 0.f};
                #pragma unroll
                for (int kk = 0; kk < 4; kk++) mma16816(acc, afr[mb][kk], b[kk]);
                float s0 = fmaf(-2.f, acc[0], enp.x), s1 = fmaf(-2.f, acc[1], enp.y);
                float s2 = fmaf(-2.f, acc[2], enp.x), s3 = fmaf(-2.f, acc[3], enp.y);
                int rA = mb * 16 + gid;
                u32* clA = &smp->clist[((warp * CHUNK + rA) * 4 + tig) * CAPL];
                u32* clB = &smp->clist[((warp * CHUNK + rA + 8) * 4 + tig) * CAPL];
                float gA = runmin[2 * mb] + eps, gB = runmin[2 * mb + 1] + eps;
                capture(clA, s0, c0 + 2 * tig,     gA, cnt[2 * mb]);
                capture(clA, s1, c0 + 2 * tig + 1, gA, cnt[2 * mb]);
                capture(clB, s2, c0 + 2 * tig,     gB, cnt[2 * mb + 1]);
                capture(clB, s3, c0 + 2 * tig + 1, gB, cnt[2 * mb + 1]);
                runmin[2 * mb]     = fminf(runmin[2 * mb],     fminf(s0, s1));
                runmin[2 * mb + 1] = fminf(runmin[2 * mb + 1], fminf(s2, s3));
            }
            #pragma unroll
            for (int rs = 0; rs < 8; rs++) {   // share mins across tig lanes
                float m = runmin[rs];
                m = fminf(m, __shfl_xor_sync(~0u, m, 1));
                m = fminf(m, __shfl_xor_sync(~0u, m, 2));
                runmin[rs] = m;
            }
        }
        #pragma unroll
        for (int rs = 0; rs < 8; rs++) {
            int row = (rs >> 1) * 16 + ((rs & 1) << 3) + gid;
            if (tig == 0) smp->rowminS[warp * CHUNK + row] = runmin[rs];
            smp->cntS[(warp * CHUNK + row) * 4 + tig] = (unsigned char)cnt[rs];
        }
        __syncwarp();

        // ---- exact verify: 2 rows/lane, reference fp32 rounding ----
        for (int rr = 0; rr < 2; rr++) {
            const int r = 2 * lane + rr, gr = warp * CHUNK + r;
            const float thr = smp->rowminS[gr] + eps;
            float4 xv[16];
            const float4* xg = (const float4*)(x + (chunkrow + r) * DDIM);
            #pragma unroll
            for (int i = 0; i < 16; i++) xv[i] = xg[i];
            const float* xr = (const float*)xv;
            float xn = 0.f;
            #pragma unroll
            for (int d = 0; d < DDIM; d++) xn = __fadd_rn(xn, __fmul_rn(xr[d], xr[d]));

            int kv[NMCAP]; int nm = 0; bool full = false;
            const u32* cb = &smp->clist[gr * 4 * CAPL];
            for (int tg = 0; tg < 4; tg++) {
                int c = smp->cntS[gr * 4 + tg];
                if (c > CAPL) { full = true; break; }
                for (int i = 0; i < c; i++) {
                    u32 e = cb[tg * CAPL + i];
                    if (__half2float(__ushort_as_half((u16)(e >> 16))) <= thr) {
                        if (nm < NMCAP) kv[nm++] = (int)(e & 0xFFFF);
                        else full = true;
                    }
                }
            }
            float bd = 3.4e38f; int bk = KCODES;
            if (!full && xn <= 256.0f) {
                for (int i = 0; i < nm; i++) {
                    int k = kv[i];
                    const float2* e2 = (const float2*)(g_embT + k * DDIM);
                    float m = 0.f;
                    #pragma unroll
                    for (int d2 = 0; d2 < 32; d2++) {
                        float2 xa = *(const float2*)&xr[2 * d2];
                        float2 ea = e2[d2];
                        m = fmaf(xa.x, ea.x, m); m = fmaf(xa.y, ea.y, m);
                    }
                    float dd = __fadd_rn(__fsub_rn(xn, 2.0f * m), smp->ens[k]);
                    if (dd < bd || (dd == bd && k < bk)) { bd = dd; bk = k; }
                }
            } else {
                for (int k = 0; k < KCODES; k++) {   // exact full scan
                    const float* e = g_embT + k * DDIM;
                    float m = 0.f;
                    #pragma unroll
                    for (int d = 0; d < DDIM; d++) m = fmaf(xr[d], e[d], m);
                    float dd = __fadd_rn(__fsub_rn(xn, 2.0f * m), smp->ens[k]);
                    if (dd < bd) { bd = dd; bk = k; }
                }
            }
            smp->codesS[gr] = (u16)bk;
            lossacc += (double)bd;
        }
        __syncwarp();

        // ---- write quantized rows (warp-local, from L1-hot g_embT) ----
        {
            float4* o4 = (float4*)(out + chunkrow * DDIM);
            const float4* e4 = (const float4*)g_embT;
            #pragma unroll 4
            for (int i = 0; i < 32; i++) {
                int q = lane + 32 * i;
                o4[q] = e4[smp->codesS[warp * CHUNK + (q >> 4)] * 16 + (q & 15)];
            }
        }
    }

    // ---- loss: deterministic reduce ----
    {
        double v = lossacc;
        #pragma unroll
        for (int o = 16; o > 0; o >>= 1) v += __shfl_xor_sync(~0u, v, o);
        if (lane == 0) smp->lossw[warp] = v;
    }
    __syncthreads();
    if (t == 0) {
        double s = 0.0;
        for (int i = 0; i < WARPS; i++) s += smp->lossw[i];
        g_partial[blockIdx.x] = s;
        __threadfence();
        unsigned old = atomicAdd(&g_count, 1u);
        smp->flag = (old == gridDim.x - 1) ? 1 : 0;
    }
    __syncthreads();
    if (smp->flag) {
        volatile double* gp = g_partial;
        if (t < MAXG) smp->red[t] = (t < (int)gridDim.x) ? gp[t] : 0.0;
        __syncthreads();
        #pragma unroll
        for (int o = 64; o > 0; o >>= 1) {
            if (t < o) smp->red[t] += smp->red[t + o];
            __syncthreads();
        }
        if (t == 0) {
            if (writeLoss) out[nelem] = (float)(smp->red[0] * 1.25 / (double)nelem);
            g_count = 0;
        }
    }
}

extern "C" void kernel_launch(void* const* d_in, const int* in_sizes, int n_in,
                              void* d_out, int out_size)
{
    const float* x   = (const float*)d_in[0];
    const float* emb = (const float*)d_in[1];
    float* out = (float*)d_out;
    long n = (long)in_sizes[0];                   // 8388608
    long nrows = n / DDIM;                        // 131072
    int grid = (int)(nrows / (CHUNK * WARPS));    // 128
    if (grid > MAXG) grid = MAXG;
    size_t smem = sizeof(SMT);                    // ~170 KB
    cudaFuncSetAttribute(vq_main, cudaFuncAttributeMaxDynamicSharedMemorySize, (int)smem);
    int writeLoss = ((long)out_size > n) ? 1 : 0;
    vq_prep<<<(DDIM * KCODES) / NTHREADS, NTHREADS>>>(emb);
    vq_main<<<grid, NTHREADS, smem>>>(x, emb, out, nrows, n, writeLoss);
}

// round 17
// speedup vs baseline: 3.8240x; 3.8240x over previous
#include <cuda_runtime.h>
#include <cuda_fp16.h>

#define DDIM 64
#define KCODES 512
#define NTHREADS 512
#define WARPS 16
#define CHUNK 64
#define HROWS 32
#define CAPL 3
#define AS 36
#define BS 36
#define MAXG 128

typedef unsigned int u32;
typedef unsigned short u16;

__device__ float  g_embT[KCODES * DDIM];
__device__ double g_partial[MAXG];
__device__ unsigned g_count;

struct SMT {
    u32   B[KCODES * BS];                    // fp16 pairs: row k, word p = d(2p,2p+1)
    u32   Aslice[WARPS * 16 * AS];           // per-warp ldmatrix staging
    u32   clistW[WARPS * HROWS * 4 * CAPL];  // per-warp candidate dump
    float ens[KCODES];
    float rowminW[WARPS * HROWS];
    float evW[WARPS * HROWS];
    u16   codesW[WARPS * HROWS];
    double lossw[WARPS];
    double red[MAXG];
    float redf[WARPS];
    float epsv;
    int   flag;
};

__device__ __forceinline__ u32 smem_u32(const void* p) {
    u32 a;
    asm("{ .reg .u64 t; cvta.to.shared.u64 t, %1; cvt.u32.u64 %0, t; }" : "=r"(a) : "l"(p));
    return a;
}
__device__ __forceinline__ void mma16816(float* c, const u32* a, const u32* b) {
    asm volatile("mma.sync.aligned.m16n8k16.row.col.f32.f16.f16.f32 "
        "{%0,%1,%2,%3},{%4,%5,%6,%7},{%8,%9},{%0,%1,%2,%3};\n"
        : "+f"(c[0]), "+f"(c[1]), "+f"(c[2]), "+f"(c[3])
        : "r"(a[0]), "r"(a[1]), "r"(a[2]), "r"(a[3]), "r"(b[0]), "r"(b[1]));
}
__device__ __forceinline__ void ldsm4(u32& a0, u32& a1, u32& a2, u32& a3, u32 addr) {
    asm volatile("ldmatrix.sync.aligned.m8n8.x4.shared.b16 {%0,%1,%2,%3}, [%4];"
                 : "=r"(a0), "=r"(a1), "=r"(a2), "=r"(a3) : "r"(addr));
}
__device__ __forceinline__ float entscore(u32 e) {
    return __half2float(__ushort_as_half((u16)(e >> 16)));
}
// keep CAPL smallest; evict-largest; evmin tracks evicted scores (f32-conservative)
__device__ __forceinline__ void cap3(u32 ent[CAPL], float s, int code, float gate, float& evmin) {
    if (s <= gate) {
        u32 ne = ((u32)__half_as_ushort(__float2half_rd(s)) << 16) | (u32)code;
        float v0 = entscore(ent[0]), v1 = entscore(ent[1]), v2 = entscore(ent[2]);
        float vm = v0; int jm = 0;
        if (v1 > vm) { vm = v1; jm = 1; }
        if (v2 > vm) { vm = v2; jm = 2; }
        if (s < vm) {
            evmin = fminf(evmin, vm);            // vm=inf placeholder -> no-op
            ent[0] = (jm == 0) ? ne : ent[0];
            ent[1] = (jm == 1) ? ne : ent[1];
            ent[2] = (jm == 2) ? ne : ent[2];
        } else {
            evmin = fminf(evmin, s);
        }
    }
}

__global__ void vq_prep(const float* __restrict__ emb)
{
    int i = blockIdx.x * blockDim.x + threadIdx.x;
    int d = i >> 9, k = i & 511;
    g_embT[k * DDIM + d] = emb[i];
}

__global__ __launch_bounds__(NTHREADS, 1)
void vq_main(const float* __restrict__ x, const float* __restrict__ emb,
             float* __restrict__ out, long nrows, long nelem, int writeLoss)
{
    extern __shared__ char smraw[];
    SMT* smp = (SMT*)smraw;
    const int t = threadIdx.x, lane = t & 31, warp = t >> 5;
    const int gid = lane >> 2, tig = lane & 3;

    // ---- prologue (only block-synced section) ----
    {
        int p = t & 31, kg = t >> 5;
        for (int j = 0; j < 32; j++) {
            int k = kg * 32 + j;
            __half2 h = __floats2half2_rn(emb[(2 * p) * KCODES + k],
                                          emb[(2 * p + 1) * KCODES + k]);
            smp->B[k * BS + p] = *(u32*)&h;
        }
    }
    {   // exact ||e_k||^2 (reference chain)
        float s = 0.f;
        #pragma unroll
        for (int d = 0; d < DDIM; d++) {
            float e = emb[d * KCODES + t];
            s = __fadd_rn(s, __fmul_rn(e, e));
        }
        smp->ens[t] = s;
    }
    __syncthreads();
    {   // eps = 0.0625*emax + 1e-3 (fp16 bound for ||x||<=16, 2x safety)
        float mx = smp->ens[t];
        #pragma unroll
        for (int o = 16; o > 0; o >>= 1) mx = fmaxf(mx, __shfl_xor_sync(~0u, mx, o));
        if (lane == 0) smp->redf[warp] = mx;
        __syncthreads();
        if (t == 0) {
            float m2 = smp->redf[0];
            for (int i = 1; i < WARPS; i++) m2 = fmaxf(m2, smp->redf[i]);
            smp->epsv = 0.0625f * sqrtf(m2) + 1e-3f;
        }
    }
    __syncthreads();

    const float eps = smp->epsv;
    const long chunkrow = ((long)blockIdx.x * WARPS + warp) * CHUNK;
    double lossacc = 0.0;

    const int matid = lane >> 3;
    const int rowoff = ((matid & 1) << 3) + (lane & 7);
    const int kcolw = (matid >> 1) << 2;
    const u32 Asl = smem_u32(&smp->Aslice[warp * 16 * AS]);
    const u32 Bu  = smem_u32(smp->B);
    const int grp = lane >> 3;
    const int khb = ((grp >> 1) << 4) + ((grp & 1) << 3);
    const u32 ENTINF = 0x7C0003FFu;

    if (chunkrow < nrows) {
        #pragma unroll 1
        for (int half = 0; half < 2; half++) {
            const long rowbase = chunkrow + half * HROWS;

            // ---- stage 32 rows -> A fragments in registers ----
            u32 afr[2][4][4];
            #pragma unroll
            for (int mb = 0; mb < 2; mb++) {
                const float4* xp = (const float4*)(x + (rowbase + mb * 16) * DDIM);
                #pragma unroll
                for (int i = 0; i < 8; i++) {
                    float4 v = xp[lane + 32 * i];
                    int q = lane + 32 * i, row = q >> 4, quad = q & 15;
                    __half2 h0 = __floats2half2_rn(v.x, v.y);
                    __half2 h1 = __floats2half2_rn(v.z, v.w);
                    uint2 u; u.x = *(u32*)&h0; u.y = *(u32*)&h1;
                    *(uint2*)&smp->Aslice[warp * 16 * AS + row * AS + quad * 2] = u;
                }
                __syncwarp();
                u32 ab = Asl + (u32)((rowoff * AS + kcolw) << 2);
                #pragma unroll
                for (int kk = 0; kk < 4; kk++)
                    ldsm4(afr[mb][kk][0], afr[mb][kk][1], afr[mb][kk][2], afr[mb][kk][3],
                          ab + (kk << 5));
                __syncwarp();
            }

            // ---- single MMA sweep over 512 codes ----
            float runmin[4], evmin[4];
            u32 ent[4][CAPL];
            #pragma unroll
            for (int i = 0; i < 4; i++) {
                runmin[i] = 3.4e38f; evmin[i] = 3.4e38f;
                ent[i][0] = ENTINF; ent[i][1] = ENTINF; ent[i][2] = ENTINF;
            }

            #pragma unroll 1
            for (int ntl = 0; ntl < 64; ntl++) {
                const int c0 = ntl * 8;
                u32 ba = Bu + (u32)(((c0 + (lane & 7)) * BS) << 2) + (u32)(khb << 1);
                u32 b[4][2];
                ldsm4(b[0][0], b[0][1], b[1][0], b[1][1], ba);
                ldsm4(b[2][0], b[2][1], b[3][0], b[3][1], ba + 64);
                float2 enp = *(const float2*)&smp->ens[c0 + 2 * tig];

                #pragma unroll
                for (int mb = 0; mb < 2; mb++) {
                    float acc[4] = {0.f, 0.f, 0.f, 0.f};
                    #pragma unroll
                    for (int kk = 0; kk < 4; kk++) mma16816(acc, afr[mb][kk], b[kk]);
                    float s0 = fmaf(-2.f, acc[0], enp.x), s1 = fmaf(-2.f, acc[1], enp.y);
                    float s2 = fmaf(-2.f, acc[2], enp.x), s3 = fmaf(-2.f, acc[3], enp.y);
                    const int rs0 = 2 * mb, rs1 = 2 * mb + 1;
                    float g0 = runmin[rs0] + eps, g1 = runmin[rs1] + eps;
                    cap3(ent[rs0], s0, c0 + 2 * tig,     g0, evmin[rs0]);
                    cap3(ent[rs0], s1, c0 + 2 * tig + 1, g0, evmin[rs0]);
                    cap3(ent[rs1], s2, c0 + 2 * tig,     g1, evmin[rs1]);
                    cap3(ent[rs1], s3, c0 + 2 * tig + 1, g1, evmin[rs1]);
                    runmin[rs0] = fminf(runmin[rs0], fminf(s0, s1));
                    runmin[rs1] = fminf(runmin[rs1], fminf(s2, s3));
                }
                #pragma unroll
                for (int rs = 0; rs < 4; rs++) {
                    float m = runmin[rs];
                    m = fminf(m, __shfl_xor_sync(~0u, m, 1));
                    m = fminf(m, __shfl_xor_sync(~0u, m, 2));
                    runmin[rs] = m;
                }
            }

            // ---- publish per-row min / evmin / entries ----
            #pragma unroll
            for (int rs = 0; rs < 4; rs++) {
                int row16 = (rs >> 1) * 16 + ((rs & 1) << 3) + gid;   // 0..31
                int idx = warp * HROWS + row16;
                float e = evmin[rs];
                e = fminf(e, __shfl_xor_sync(~0u, e, 1));
                e = fminf(e, __shfl_xor_sync(~0u, e, 2));
                if (tig == 0) { smp->rowminW[idx] = runmin[rs]; smp->evW[idx] = e; }
                #pragma unroll
                for (int j = 0; j < CAPL; j++)
                    smp->clistW[(idx * 4 + tig) * CAPL + j] = ent[rs][j];
            }
            __syncwarp();

            // ---- exact verify: 1 row per lane ----
            const int gr = warp * HROWS + lane;
            const float thr = smp->rowminW[gr] + eps;
            float4 xv[16];
            const float4* xg = (const float4*)(x + (rowbase + lane) * DDIM);
            #pragma unroll
            for (int i = 0; i < 16; i++) xv[i] = xg[i];
            const float* xr = (const float*)xv;
            float xn = 0.f;   // exact ||x||^2 chain
            #pragma unroll
            for (int d = 0; d < DDIM; d++) xn = __fadd_rn(xn, __fmul_rn(xr[d], xr[d]));

            bool full = (smp->evW[gr] <= thr) || (xn > 256.0f);
            float bd = 3.4e38f; int bk = KCODES;
            if (!full) {
                const u32* cb = &smp->clistW[gr * 4 * CAPL];
                #pragma unroll 1
                for (int ip = 0; ip < 6; ip++) {           // 12 slots, ILP-2 pairs
                    u32 e1 = cb[2 * ip], e2 = cb[2 * ip + 1];
                    bool p1 = entscore(e1) <= thr, p2 = entscore(e2) <= thr;
                    if (p1 || p2) {
                        int k1 = (int)(e1 & 0xFFFF), k2 = (int)(e2 & 0xFFFF);
                        if (!p1) k1 = k2;
                        if (!p2) k2 = k1;
                        const float2* ea = (const float2*)(g_embT + k1 * DDIM);
                        const float2* eb = (const float2*)(g_embT + k2 * DDIM);
                        float m1 = 0.f, m2 = 0.f;
                        #pragma unroll
                        for (int d2 = 0; d2 < 32; d2++) {
                            float2 xa = *(const float2*)&xr[2 * d2];
                            float2 va = ea[d2], vb = eb[d2];
                            m1 = fmaf(xa.x, va.x, m1); m1 = fmaf(xa.y, va.y, m1);
                            m2 = fmaf(xa.x, vb.x, m2); m2 = fmaf(xa.y, vb.y, m2);
                        }
                        float d1 = __fadd_rn(__fsub_rn(xn, 2.0f * m1), smp->ens[k1]);
                        float d2v = __fadd_rn(__fsub_rn(xn, 2.0f * m2), smp->ens[k2]);
                        if (p1 && (d1 < bd || (d1 == bd && k1 < bk)))  { bd = d1;  bk = k1; }
                        if (p2 && (d2v < bd || (d2v == bd && k2 < bk))) { bd = d2v; bk = k2; }
                    }
                }
            }
            // ---- rare fallback: warp-cooperative exact full scan ----
            unsigned bal = __ballot_sync(~0u, full);
            while (bal) {
                int r = __ffs(bal) - 1; bal &= bal - 1;
                const float* xgr = x + (rowbase + r) * DDIM;
                float xnr = __shfl_sync(~0u, xn, r);
                float bd2 = 3.4e38f; int bk2 = KCODES;
                for (int kk = lane; kk < KCODES; kk += 32) {
                    const float* e = g_embT + kk * DDIM;
                    float m = 0.f;
                    #pragma unroll
                    for (int d = 0; d < DDIM; d++) m = fmaf(xgr[d], e[d], m);
                    float dd = __fadd_rn(__fsub_rn(xnr, 2.0f * m), smp->ens[kk]);
                    if (dd < bd2 || (dd == bd2 && kk < bk2)) { bd2 = dd; bk2 = kk; }
                }
                #pragma unroll
                for (int o = 16; o > 0; o >>= 1) {   // lexicographic (d,k)
                    float od = __shfl_xor_sync(~0u, bd2, o);
                    int ok2 = __shfl_xor_sync(~0u, bk2, o);
                    if (od < bd2 || (od == bd2 && ok2 < bk2)) { bd2 = od; bk2 = ok2; }
                }
                if (lane == r) { bd = bd2; bk = bk2; }
            }
            smp->codesW[gr] = (u16)bk;
            lossacc += (double)bd;
            __syncwarp();

            // ---- write quantized rows (coalesced) ----
            float4* o4 = (float4*)(out + rowbase * DDIM);
            const float4* e4 = (const float4*)g_embT;
            #pragma unroll
            for (int i = 0; i < 16; i++) {
                int q = lane + 32 * i;
                o4[q] = e4[smp->codesW[warp * HROWS + (q >> 4)] * 16 + (q & 15)];
            }
            __syncwarp();
        }
    }

    // ---- loss: deterministic reduce ----
    {
        double v = lossacc;
        #pragma unroll
        for (int o = 16; o > 0; o >>= 1) v += __shfl_xor_sync(~0u, v, o);
        if (lane == 0) smp->lossw[warp] = v;
    }
    __syncthreads();
    if (t == 0) {
        double s = 0.0;
        for (int i = 0; i < WARPS; i++) s += smp->lossw[i];
        g_partial[blockIdx.x] = s;
        __threadfence();
        unsigned old = atomicAdd(&g_count, 1u);
        smp->flag = (old == gridDim.x - 1) ? 1 : 0;
    }
    __syncthreads();
    if (smp->flag) {
        volatile double* gp = g_partial;
        if (t < MAXG) smp->red[t] = (t < (int)gridDim.x) ? gp[t] : 0.0;
        __syncthreads();
        #pragma unroll
        for (int o = 64; o > 0; o >>= 1) {
            if (t < o) smp->red[t] += smp->red[t + o];
            __syncthreads();
        }
        if (t == 0) {
            if (writeLoss) out[nelem] = (float)(smp->red[0] * 1.25 / (double)nelem);
            g_count = 0;
        }
    }
}

extern "C" void kernel_launch(void* const* d_in, const int* in_sizes, int n_in,
                              void* d_out, int out_size)
{
    const float* x   = (const float*)d_in[0];
    const float* emb = (const float*)d_in[1];
    float* out = (float*)d_out;
    long n = (long)in_sizes[0];                   // 8388608
    long nrows = n / DDIM;                        // 131072
    int grid = (int)((nrows + CHUNK * WARPS - 1) / (CHUNK * WARPS));   // 128
    if (grid > MAXG) grid = MAXG;
    size_t smem = sizeof(SMT);                    // ~144 KB
    cudaFuncSetAttribute(vq_main, cudaFuncAttributeMaxDynamicSharedMemorySize, (int)smem);
    int writeLoss = ((long)out_size > n) ? 1 : 0;
    vq_prep<<<(DDIM * KCODES) / NTHREADS, NTHREADS>>>(emb);
    vq_main<<<grid, NTHREADS, smem>>>(x, emb, out, nrows, n, writeLoss);
}